// round 11
// baseline (speedup 1.0000x reference)
#include <cuda_runtime.h>
#include <cuda_fp16.h>
#include <cstdint>
#include <cstddef>

#define BATCH 32
#define CTOT 512
#define BR 256
#define LLEN 4096
#define TN 62            // output columns per tile
#define NCOL 64          // TN + 2 halo columns
#define SBW 136          // fp16 B-tile col stride in 32-bit words (≡8 mod 32)
#define NTHREADS 256
#define LTILES 67        // ceil(4096/62)
#define BN_EPS 1e-5f
#define DET_BLOCKS 128

// ---------------- device scratch (allocation-free) ----------------
__device__ unsigned g_blkA[DET_BLOCKS], g_blkB[DET_BLOCKS];
// fragment-major weight images: [wb(8)][it(16)][lane(32)][8 words], fully coalesced
__device__ unsigned g_w1f[8 * 16 * 32 * 8], g_w3f[8 * 16 * 32 * 8];

// word permutation within 8-word (k16) group (X2 B-tile): word tg -> 2tg, tg+4 -> 2tg+1
__host__ __device__ __forceinline__ int wperm(int w) {
    return (w & ~7) | ((w & 3) << 1) | ((w >> 2) & 1);
}
// k-position permutation for the Y2/W3 reduction dim:
// p = 32*warp + 4*g + q  <->  channel = 32*warp + 8*q + g
__host__ __device__ __forceinline__ int kinv(int p) {
    int w = p >> 5, r = p & 31;
    return 32 * w + 8 * (r & 3) + (r >> 2);
}

__device__ __forceinline__ unsigned packh2(float lo, float hi) {
    __half2 h = __floats2half2_rn(lo, hi);
    return *reinterpret_cast<unsigned*>(&h);
}

// mish(x) = x * tanh(softplus(x)) = x * (z^2-1)/(z^2+1), z = 1+exp(x)
__device__ __forceinline__ float mishf(float x) {
    if (x > 30.f) return x;
    float z = 1.f + __expf(x);
    float z2 = z * z;
    return x * __fdividef(z2 - 1.f, z2 + 1.f);
}

__device__ __forceinline__ void mma16(float* c, const unsigned* a, unsigned b0, unsigned b1) {
    asm volatile(
        "mma.sync.aligned.m16n8k16.row.col.f32.f16.f16.f32 "
        "{%0,%1,%2,%3}, {%4,%5,%6,%7}, {%8,%9}, {%0,%1,%2,%3};\n"
        : "+f"(c[0]), "+f"(c[1]), "+f"(c[2]), "+f"(c[3])
        : "r"(a[0]), "r"(a[1]), "r"(a[2]), "r"(a[3]), "r"(b0), "r"(b1));
}

// ------- mask dtype detection + fragment-major fp16 weight image build -------
__global__ void detect_kernel(const unsigned char* __restrict__ m,
                              const float* __restrict__ w1,
                              const float* __restrict__ w3) {
    unsigned a = 0, b = 0;
    const int stride = DET_BLOCKS * 256;
    int gtid = blockIdx.x * 256 + threadIdx.x;
    for (int i = gtid; i < BATCH * LLEN; i += stride) {
        unsigned v = m[i];
        if ((i & 3) == 0) a |= v; else b |= v;
    }
    a = __reduce_or_sync(0xffffffffu, a);
    b = __reduce_or_sync(0xffffffffu, b);
    __shared__ unsigned sa[8], sb[8];
    int w = threadIdx.x >> 5;
    if ((threadIdx.x & 31) == 0) { sa[w] = a; sb[w] = b; }
    __syncthreads();
    if (threadIdx.x == 0) {
        unsigned A = 0, B = 0;
        #pragma unroll
        for (int i = 0; i < 8; i++) { A |= sa[i]; B |= sb[i]; }
        g_blkA[blockIdx.x] = A; g_blkB[blockIdx.x] = B;
    }
    // fragment-major images: i = ((wb*16+it)*32+lane)*8 + j
    // W1: standard k (X2 tile is wperm'd).  W3: k permuted by kinv (Y2 tile is identity).
    for (int i = gtid; i < 32768; i += stride) {
        int j = i & 7, lane = (i >> 3) & 31, it = (i >> 8) & 15, wb_ = i >> 12;
        int g = lane >> 2, tg = lane & 3;
        int q = j >> 1;
        int row = wb_ * 32 + g + q * 8;
        // W1 entry: word wo holds k = 2wo, 2wo+1
        int wo = it * 8 + tg + ((j & 1) ? 4 : 0);
        g_w1f[i] = packh2(w1[row * 256 + 2 * wo], w1[row * 256 + 2 * wo + 1]);
        // W3 entry: mainloop loads words (8it+2tg, +1) => k-pos (16it+4tg .. +3)
        int pos = 16 * it + 4 * tg + 2 * (j & 1);
        g_w3f[i] = packh2(w3[row * 256 + kinv(pos)], w3[row * 256 + kinv(pos + 1)]);
    }
}

// ---------------- fused main kernel ----------------
__global__ void __launch_bounds__(NTHREADS, 4) fused_kernel(
    const float* __restrict__ x, const void* __restrict__ mk,
    const float* __restrict__ b1w, const float* __restrict__ b1b,
    const float* __restrict__ b1m, const float* __restrict__ b1v,
    const float* __restrict__ b2w, const float* __restrict__ b2b,
    const float* __restrict__ b2m, const float* __restrict__ b2v,
    const float* __restrict__ b3w, const float* __restrict__ b3b,
    const float* __restrict__ b3m, const float* __restrict__ b3v,
    const float* __restrict__ w2,
    float* __restrict__ out)
{
    extern __shared__ unsigned smem[];
    unsigned* sB = smem;                        // [NCOL][SBW] fp16 tile (X2 -> Y1 -> Y2)
    __shared__ float sS1[BR], sT1[BR], sS2[BR], sT2[BR], sS3[BR], sT3[BR];
    __shared__ float sWa[BR], sWb[BR], sWc[BR];   // indexed by k-pos p
    __shared__ unsigned char sMk[NCOL + 4];
    __shared__ int sMode;

    const int tid = threadIdx.x;
    const int bb = blockIdx.y;
    const int l0 = blockIdx.x * TN;

    // mask dtype mode (reduce detect blocks' partials)
    if (tid < 32) {
        unsigned A = 0, B = 0;
        for (int i = tid; i < DET_BLOCKS; i += 32) { A |= g_blkA[i]; B |= g_blkB[i]; }
        A = __reduce_or_sync(0xffffffffu, A);
        B = __reduce_or_sync(0xffffffffu, B);
        if (tid == 0) sMode = (A == 0) ? 2 : ((B == 0) ? 0 : 1);
    }
    // per-channel fused BN constants; conv constants permuted to k-pos indexing
    {
        int ch = tid;
        float i1 = rsqrtf(b1v[ch] + BN_EPS); float s1 = b1w[ch] * i1;
        sS1[ch] = s1; sT1[ch] = b1b[ch] - s1 * b1m[ch];
        float i3 = rsqrtf(b3v[ch] + BN_EPS); float s3 = b3w[ch] * i3;
        sS3[ch] = s3; sT3[ch] = b3b[ch] - s3 * b3m[ch];
        int pc = kinv(tid);   // channel living at k-pos tid
        float i2 = rsqrtf(b2v[pc] + BN_EPS); float s2 = b2w[pc] * i2;
        sS2[tid] = s2; sT2[tid] = b2b[pc] - s2 * b2m[pc];
        sWa[tid] = w2[pc * 3 + 0]; sWb[tid] = w2[pc * 3 + 1]; sWc[tid] = w2[pc * 3 + 2];
    }

    // load X2 tile (cols l0-1 .. l0+62): pack k-pairs to fp16, word-permuted
    {
        const float* xb = x + ((size_t)bb * CTOT + BR) * LLEN;
        #pragma unroll 4
        for (int idx = tid; idx < 128 * NCOL; idx += NTHREADS) {
            int w = idx >> 6, n = idx & 63;
            int l = l0 - 1 + n;
            float v0 = 0.f, v1 = 0.f;
            if (l >= 0 && l < LLEN) {
                const float* p = xb + (size_t)(2 * w) * LLEN + l;
                v0 = p[0]; v1 = p[LLEN];
            }
            sB[n * SBW + wperm(w)] = packh2(v0, v1);
        }
    }
    // copy x1 into odd output channels (independent work)
    {
        const float* x1b = x + (size_t)bb * CTOT * LLEN;
        float* ob = out + (size_t)bb * CTOT * LLEN;
        #pragma unroll 4
        for (int idx = tid; idx < BR * NCOL; idx += NTHREADS) {
            int r = idx >> 6, c = idx & 63;
            int l = l0 + c;
            if (c < TN && l < LLEN)
                ob[(size_t)(2 * r + 1) * LLEN + l] = x1b[(size_t)r * LLEN + l];
        }
    }
    __syncthreads();

    // fill per-tile mask bytes (needs sMode; consumed after next sync)
    if (tid < NCOL + 4) {
        int l = l0 - 1 + tid;
        unsigned char v = 0;
        if (tid < NCOL && l >= 0 && l < LLEN) {
            int mode = sMode;
            size_t i = (size_t)bb * LLEN + l;
            if (mode == 0)      v = (((const int*)mk)[i] != 0);
            else if (mode == 1) v = (((const unsigned char*)mk)[i] != 0);
            else                v = (((const float*)mk)[i] != 0.f);
        }
        sMk[tid] = v;
    }

    const int warp = tid >> 5, lane = tid & 31;
    const int g = lane >> 2, tg = lane & 3;
    const int m0 = warp * 32;
    const int rows4[4] = { m0 + g, m0 + g + 8, m0 + 16 + g, m0 + 24 + g };
    // fragment-major A base: warp*4096 + lane*8 (per it: +256 words)
    const int abase = warp * 4096 + lane * 8;
    // epilogue-1 pack base: k-pos of this thread's 4 rows = 32*warp+4g .. +3 -> word offset
    const int kwoff = 16 * warp + 2 * g;

    float acc[2][4][4];    // [mt][nt-in-half][q] — 32 accumulators

    // ================ GEMM1: Y1 = W1 @ X2, two N-halves, packed fp16 in-place ================
    #pragma unroll
    for (int h = 0; h < 2; h++) {
        #pragma unroll
        for (int mt = 0; mt < 2; mt++)
            #pragma unroll
            for (int nt = 0; nt < 4; nt++)
                #pragma unroll
                for (int q = 0; q < 4; q++) acc[mt][nt][q] = 0.f;
        {
            const unsigned* wp = g_w1f + abase;
            #pragma unroll
            for (int it = 0; it < 16; it++) {
                uint4 q1 = *(const uint4*)(wp + it * 256);
                uint4 q2 = *(const uint4*)(wp + it * 256 + 4);
                unsigned a0[4] = { q1.x, q1.z, q1.y, q1.w };
                unsigned a1[4] = { q2.x, q2.z, q2.y, q2.w };
                const int kw = it * 8 + 2 * tg;
                #pragma unroll
                for (int nt = 0; nt < 4; nt++) {
                    uint2 Bv = *(const uint2*)&sB[((h * 4 + nt) * 8 + g) * SBW + kw];
                    mma16(acc[0][nt], a0, Bv.x, Bv.y);
                    mma16(acc[1][nt], a1, Bv.x, Bv.y);
                }
            }
        }
        __syncthreads();   // all warps done reading this half's cols
        // epilogue: mish + bn1 + mask -> k-packed fp16 (one STS.64 per column)
        {
            float sv[4], tv[4];
            #pragma unroll
            for (int q = 0; q < 4; q++) { sv[q] = sS1[rows4[q]]; tv[q] = sT1[rows4[q]]; }
            #pragma unroll
            for (int nt = 0; nt < 4; nt++)
                #pragma unroll
                for (int e = 0; e < 2; e++) {
                    int col = (h * 4 + nt) * 8 + 2 * tg + e;
                    float z0 = sv[0] * mishf(acc[0][nt][e])     + tv[0];
                    float z1 = sv[1] * mishf(acc[0][nt][2 + e]) + tv[1];
                    float z2 = sv[2] * mishf(acc[1][nt][e])     + tv[2];
                    float z3 = sv[3] * mishf(acc[1][nt][2 + e]) + tv[3];
                    if (!sMk[col]) { z0 = z1 = z2 = z3 = 0.f; }
                    uint2 pk;
                    pk.x = packh2(z0, z1);
                    pk.y = packh2(z2, z3);
                    *(uint2*)&sB[col * SBW + kwoff] = pk;
                }
        }
    }
    __syncthreads();   // epi of half 1 visible to all

    // ------- depthwise conv3 + bn2 + mask, word-paired channels, in place -------
    // thread t handles word t (k-pos 2t, 2t+1); seg 0 -> cols 0..30, seg 1 -> cols 31..61.
    // cols 62,63 keep stale Y1; GEMM3 garbage there is never stored (c0 <= 60).
    {
        const int t = tid & 127, seg = tid >> 7;
        float wax = sWa[2 * t], way = sWa[2 * t + 1];
        float wbx = sWb[2 * t], wby = sWb[2 * t + 1];
        float wcx = sWc[2 * t], wcy = sWc[2 * t + 1];
        float s2x = sS2[2 * t], s2y = sS2[2 * t + 1];
        float t2x = sT2[2 * t], t2y = sT2[2 * t + 1];
        unsigned* wrd = sB + t;

        float2 pre31, pre32;
        if (seg == 0) {
            __half2 h31 = *(__half2*)&wrd[31 * SBW];
            __half2 h32 = *(__half2*)&wrd[32 * SBW];
            pre31 = __half22float2(h31);
            pre32 = __half22float2(h32);
        }
        __syncthreads();   // seg0 halo reads complete before seg1 writes cols 31,32

        int j0 = seg ? 31 : 0;
        __half2 h0 = *(__half2*)&wrd[j0 * SBW];
        __half2 h1 = *(__half2*)&wrd[(j0 + 1) * SBW];
        float2 p0 = __half22float2(h0), p1 = __half22float2(h1);
        #pragma unroll 2
        for (int j = j0; j < j0 + 31; j++) {
            float2 p2;
            if (seg == 0 && j == 29)      p2 = pre31;
            else if (seg == 0 && j == 30) p2 = pre32;
            else {
                __half2 h2v = *(__half2*)&wrd[(j + 2) * SBW];
                p2 = __half22float2(h2v);
            }
            float cx = wax * p0.x + wbx * p1.x + wcx * p2.x;
            float cy = way * p0.y + wby * p1.y + wcy * p2.y;
            float vx = s2x * cx + t2x, vy = s2y * cy + t2y;
            if (!sMk[j + 1]) { vx = 0.f; vy = 0.f; }
            wrd[j * SBW] = packh2(vx, vy);
            p0 = p1; p1 = p2;
        }
    }
    __syncthreads();

    // ================ GEMM3: O = W3 @ Y2, two N-halves, direct global ================
    {
        float* ob = out + (size_t)bb * CTOT * LLEN;
        #pragma unroll
        for (int h = 0; h < 2; h++) {
            #pragma unroll
            for (int mt = 0; mt < 2; mt++)
                #pragma unroll
                for (int nt = 0; nt < 4; nt++)
                    #pragma unroll
                    for (int q = 0; q < 4; q++) acc[mt][nt][q] = 0.f;
            {
                const unsigned* wp = g_w3f + abase;
                #pragma unroll
                for (int it = 0; it < 16; it++) {
                    uint4 q1 = *(const uint4*)(wp + it * 256);
                    uint4 q2 = *(const uint4*)(wp + it * 256 + 4);
                    unsigned a0[4] = { q1.x, q1.z, q1.y, q1.w };
                    unsigned a1[4] = { q2.x, q2.z, q2.y, q2.w };
                    const int kw = it * 8 + 2 * tg;
                    #pragma unroll
                    for (int nt = 0; nt < 4; nt++) {
                        uint2 Bv = *(const uint2*)&sB[((h * 4 + nt) * 8 + g) * SBW + kw];
                        mma16(acc[0][nt], a0, Bv.x, Bv.y);
                        mma16(acc[1][nt], a1, Bv.x, Bv.y);
                    }
                }
            }
            // epilogue: mish + bn3 + mask -> even output channels, STG.64 pairs
            {
                float sv[4], tv[4];
                #pragma unroll
                for (int q = 0; q < 4; q++) { sv[q] = sS3[rows4[q]]; tv[q] = sT3[rows4[q]]; }
                #pragma unroll
                for (int mt = 0; mt < 2; mt++)
                    #pragma unroll
                    for (int nt = 0; nt < 4; nt++)
                        #pragma unroll
                        for (int qp = 0; qp < 2; qp++) {
                            int ri = mt * 2 + qp;
                            int c0 = (h * 4 + nt) * 8 + 2 * tg;
                            int l = l0 + c0;
                            if (c0 < TN - 1 && l + 1 < LLEN) {
                                float y0 = mishf(acc[mt][nt][2 * qp + 0]);
                                float y1 = mishf(acc[mt][nt][2 * qp + 1]);
                                float z0 = sv[ri] * y0 + tv[ri];
                                float z1 = sv[ri] * y1 + tv[ri];
                                float2 zz;
                                zz.x = sMk[c0 + 1] ? z0 : 0.f;
                                zz.y = sMk[c0 + 2] ? z1 : 0.f;
                                *(float2*)&ob[(size_t)(2 * rows4[ri]) * LLEN + l] = zz;
                            }
                        }
            }
        }
    }
}

// ---------------- launch ----------------
extern "C" void kernel_launch(void* const* d_in, const int* in_sizes, int n_in,
                              void* d_out, int out_size) {
    (void)in_sizes; (void)n_in; (void)out_size;
    const float* x   = (const float*)d_in[0];
    const void*  mk  = d_in[1];
    const float* w1  = (const float*)d_in[2];
    const float* w2  = (const float*)d_in[3];
    const float* w3  = (const float*)d_in[4];
    const float* b1w = (const float*)d_in[5];
    const float* b1b = (const float*)d_in[6];
    const float* b1m = (const float*)d_in[7];
    const float* b1v = (const float*)d_in[8];
    const float* b2w = (const float*)d_in[9];
    const float* b2b = (const float*)d_in[10];
    const float* b2m = (const float*)d_in[11];
    const float* b2v = (const float*)d_in[12];
    const float* b3w = (const float*)d_in[13];
    const float* b3b = (const float*)d_in[14];
    const float* b3m = (const float*)d_in[15];
    const float* b3v = (const float*)d_in[16];
    float* out = (float*)d_out;

    const int smem_bytes = NCOL * SBW * (int)sizeof(unsigned);
    cudaFuncSetAttribute(fused_kernel, cudaFuncAttributeMaxDynamicSharedMemorySize, smem_bytes);

    detect_kernel<<<DET_BLOCKS, 256>>>((const unsigned char*)mk, w1, w3);

    dim3 grid(LTILES, BATCH);
    fused_kernel<<<grid, NTHREADS, smem_bytes>>>(
        x, mk,
        b1w, b1b, b1m, b1v,
        b2w, b2b, b2m, b2v,
        b3w, b3b, b3m, b3v,
        w2, out);
}

// round 12
// speedup vs baseline: 1.0653x; 1.0653x over previous
#include <cuda_runtime.h>
#include <cuda_fp16.h>
#include <cstdint>
#include <cstddef>

#define BATCH 32
#define CTOT 512
#define BR 256
#define LLEN 4096
#define TN 62            // output columns per tile
#define NCOL 64          // TN + 2 halo columns
#define SBW 136          // fp16 B-tile col stride in 32-bit words (≡8 mod 32)
#define NTHREADS 256
#define LTILES 67        // ceil(4096/62)
#define BN_EPS 1e-5f
#define DET_BLOCKS 128

// ---------------- device scratch (allocation-free) ----------------
__device__ unsigned g_blkA[DET_BLOCKS], g_blkB[DET_BLOCKS];
// fragment-major weight images: [wb(8)][it(16)][lane(32)][8 words], fully coalesced
__device__ unsigned g_w1f[8 * 16 * 32 * 8], g_w3f[8 * 16 * 32 * 8];

// word permutation within 8-word (k16) group: orig word tg -> 2tg, tg+4 -> 2tg+1
__host__ __device__ __forceinline__ int wperm(int w) {
    return (w & ~7) | ((w & 3) << 1) | ((w >> 2) & 1);
}
// inverse: logical word v -> original channel-pair word
__host__ __device__ __forceinline__ int winv(int v) {
    return (v & ~7) | ((v & 1) << 2) | ((v >> 1) & 3);
}
// k-position permutation for the Y2/W3 reduction dim:
// p = 32*warp + 4*g + q  <->  channel = 32*warp + 8*q + g
__host__ __device__ __forceinline__ int kinv(int p) {
    int w = p >> 5, r = p & 31;
    return 32 * w + 8 * (r & 3) + (r >> 2);
}

__device__ __forceinline__ unsigned packh2(float lo, float hi) {
    __half2 h = __floats2half2_rn(lo, hi);
    return *reinterpret_cast<unsigned*>(&h);
}

// mish(x) = x * tanh(softplus(x)) = x * (z^2-1)/(z^2+1), z = 1+exp(x)
__device__ __forceinline__ float mishf(float x) {
    if (x > 30.f) return x;
    float z = 1.f + __expf(x);
    float z2 = z * z;
    return x * __fdividef(z2 - 1.f, z2 + 1.f);
}

__device__ __forceinline__ void mma16(float* c, const unsigned* a, unsigned b0, unsigned b1) {
    asm volatile(
        "mma.sync.aligned.m16n8k16.row.col.f32.f16.f16.f32 "
        "{%0,%1,%2,%3}, {%4,%5,%6,%7}, {%8,%9}, {%0,%1,%2,%3};\n"
        : "+f"(c[0]), "+f"(c[1]), "+f"(c[2]), "+f"(c[3])
        : "r"(a[0]), "r"(a[1]), "r"(a[2]), "r"(a[3]), "r"(b0), "r"(b1));
}

// ------- mask dtype detection + fragment-major fp16 weight image build -------
__global__ void detect_kernel(const unsigned char* __restrict__ m,
                              const float* __restrict__ w1,
                              const float* __restrict__ w3) {
    unsigned a = 0, b = 0;
    const int stride = DET_BLOCKS * 256;
    int gtid = blockIdx.x * 256 + threadIdx.x;
    for (int i = gtid; i < BATCH * LLEN; i += stride) {
        unsigned v = m[i];
        if ((i & 3) == 0) a |= v; else b |= v;
    }
    a = __reduce_or_sync(0xffffffffu, a);
    b = __reduce_or_sync(0xffffffffu, b);
    __shared__ unsigned sa[8], sb[8];
    int w = threadIdx.x >> 5;
    if ((threadIdx.x & 31) == 0) { sa[w] = a; sb[w] = b; }
    __syncthreads();
    if (threadIdx.x == 0) {
        unsigned A = 0, B = 0;
        #pragma unroll
        for (int i = 0; i < 8; i++) { A |= sa[i]; B |= sb[i]; }
        g_blkA[blockIdx.x] = A; g_blkB[blockIdx.x] = B;
    }
    // fragment-major images: i = ((wb*16+it)*32+lane)*8 + j
    // W1: standard k (X2 tile is wperm'd).  W3: k permuted by kinv (Y2 tile is identity).
    for (int i = gtid; i < 32768; i += stride) {
        int j = i & 7, lane = (i >> 3) & 31, it = (i >> 8) & 15, wb_ = i >> 12;
        int g = lane >> 2, tg = lane & 3;
        int q = j >> 1;
        int row = wb_ * 32 + g + q * 8;
        int wo = it * 8 + tg + ((j & 1) ? 4 : 0);
        g_w1f[i] = packh2(w1[row * 256 + 2 * wo], w1[row * 256 + 2 * wo + 1]);
        int pos = 16 * it + 4 * tg + 2 * (j & 1);
        g_w3f[i] = packh2(w3[row * 256 + kinv(pos)], w3[row * 256 + kinv(pos + 1)]);
    }
}

// ---------------- fused main kernel ----------------
__global__ void __launch_bounds__(NTHREADS, 4) fused_kernel(
    const float* __restrict__ x, const void* __restrict__ mk,
    const float* __restrict__ b1w, const float* __restrict__ b1b,
    const float* __restrict__ b1m, const float* __restrict__ b1v,
    const float* __restrict__ b2w, const float* __restrict__ b2b,
    const float* __restrict__ b2m, const float* __restrict__ b2v,
    const float* __restrict__ b3w, const float* __restrict__ b3b,
    const float* __restrict__ b3m, const float* __restrict__ b3v,
    const float* __restrict__ w2,
    float* __restrict__ out)
{
    extern __shared__ unsigned smem[];
    unsigned* sB = smem;                        // [NCOL][SBW] fp16 tile, pair-XOR swizzled
    __shared__ float sS1[BR], sT1[BR], sS2[BR], sT2[BR], sS3[BR], sT3[BR];
    __shared__ float sWa[BR], sWb[BR], sWc[BR];   // indexed by k-pos p
    __shared__ unsigned char sMk[NCOL + 4];
    __shared__ int sMode;

    const int tid = threadIdx.x;
    const int bb = blockIdx.y;
    const int l0 = blockIdx.x * TN;

    // mask dtype mode (reduce detect blocks' partials)
    if (tid < 32) {
        unsigned A = 0, B = 0;
        for (int i = tid; i < DET_BLOCKS; i += 32) { A |= g_blkA[i]; B |= g_blkB[i]; }
        A = __reduce_or_sync(0xffffffffu, A);
        B = __reduce_or_sync(0xffffffffu, B);
        if (tid == 0) sMode = (A == 0) ? 2 : ((B == 0) ? 0 : 1);
    }
    // per-channel fused BN constants; conv constants permuted to k-pos indexing
    {
        int ch = tid;
        float i1 = rsqrtf(b1v[ch] + BN_EPS); float s1 = b1w[ch] * i1;
        sS1[ch] = s1; sT1[ch] = b1b[ch] - s1 * b1m[ch];
        float i3 = rsqrtf(b3v[ch] + BN_EPS); float s3 = b3w[ch] * i3;
        sS3[ch] = s3; sT3[ch] = b3b[ch] - s3 * b3m[ch];
        int pc = kinv(tid);   // channel living at k-pos tid
        float i2 = rsqrtf(b2v[pc] + BN_EPS); float s2 = b2w[pc] * i2;
        sS2[tid] = s2; sT2[tid] = b2b[pc] - s2 * b2m[pc];
        sWa[tid] = w2[pc * 3 + 0]; sWb[tid] = w2[pc * 3 + 1]; sWc[tid] = w2[pc * 3 + 2];
    }

    // ---- X2 staging: logical pair Pl of col n at physical pair Pl ^ ql(n) ----
    // logical words (2Pl, 2Pl+1) hold channel pairs of orig words w0, w0+4.
    {
        const float* xb = x + ((size_t)bb * CTOT + BR) * LLEN;
        #pragma unroll 4
        for (int idx = tid; idx < 64 * 64; idx += NTHREADS) {
            int Pl = idx >> 6, n = idx & 63;
            int w0 = winv(2 * Pl);          // winv(2Pl+1) == w0 + 4
            int l = l0 - 1 + n;
            float a0 = 0.f, a1 = 0.f, a2 = 0.f, a3 = 0.f;
            if (l >= 0 && l < LLEN) {
                const float* p = xb + (size_t)(2 * w0) * LLEN + l;
                a0 = p[0]; a1 = p[LLEN];
                a2 = p[8 * LLEN]; a3 = p[9 * LLEN];
            }
            int Pp = Pl ^ ((n >> 2) & 3);
            uint2 pk;
            pk.x = packh2(a0, a1);
            pk.y = packh2(a2, a3);
            *(uint2*)&sB[n * SBW + 2 * Pp] = pk;
        }
    }
    // copy x1 into odd output channels (float2, independent work)
    {
        const float* x1b = x + (size_t)bb * CTOT * LLEN;
        float* ob = out + (size_t)bb * CTOT * LLEN;
        #pragma unroll 4
        for (int idx = tid; idx < BR * 32; idx += NTHREADS) {
            int r = idx >> 5, cp = idx & 31;
            int l = l0 + 2 * cp;
            if (cp < 31 && l < LLEN - 1)
                *(float2*)&ob[(size_t)(2 * r + 1) * LLEN + l] =
                    *(const float2*)&x1b[(size_t)r * LLEN + l];
        }
    }
    __syncthreads();

    // fill per-tile mask bytes (needs sMode; consumed after next sync)
    if (tid < NCOL + 4) {
        int l = l0 - 1 + tid;
        unsigned char v = 0;
        if (tid < NCOL && l >= 0 && l < LLEN) {
            int mode = sMode;
            size_t i = (size_t)bb * LLEN + l;
            if (mode == 0)      v = (((const int*)mk)[i] != 0);
            else if (mode == 1) v = (((const unsigned char*)mk)[i] != 0);
            else                v = (((const float*)mk)[i] != 0.f);
        }
        sMk[tid] = v;
    }

    const int warp = tid >> 5, lane = tid & 31;
    const int g = lane >> 2, tg = lane & 3;
    const int m0 = warp * 32;
    const int rows4[4] = { m0 + g, m0 + g + 8, m0 + 16 + g, m0 + 24 + g };
    const int abase = warp * 4096 + lane * 8;

    float acc[2][4][4];    // [mt][nt-in-half][q] — 32 accumulators

    // ================ GEMM1: Y1 = W1 @ X2, two N-halves, packed fp16 in-place ================
    #pragma unroll
    for (int h = 0; h < 2; h++) {
        #pragma unroll
        for (int mt = 0; mt < 2; mt++)
            #pragma unroll
            for (int nt = 0; nt < 4; nt++)
                #pragma unroll
                for (int q = 0; q < 4; q++) acc[mt][nt][q] = 0.f;
        {
            const unsigned* wp = g_w1f + abase;
            #pragma unroll
            for (int it = 0; it < 16; it++) {
                uint4 q1 = *(const uint4*)(wp + it * 256);
                uint4 q2 = *(const uint4*)(wp + it * 256 + 4);
                unsigned a0[4] = { q1.x, q1.z, q1.y, q1.w };
                unsigned a1[4] = { q2.x, q2.z, q2.y, q2.w };
                #pragma unroll
                for (int nt = 0; nt < 4; nt++) {
                    const int col = (h * 4 + nt) * 8 + g;
                    const int tw = 2 * (tg ^ ((col >> 2) & 3));
                    uint2 Bv = *(const uint2*)&sB[col * SBW + it * 8 + tw];
                    mma16(acc[0][nt], a0, Bv.x, Bv.y);
                    mma16(acc[1][nt], a1, Bv.x, Bv.y);
                }
            }
        }
        __syncthreads();   // all warps done reading this half's cols
        // epilogue: mish + bn1 + mask -> k-packed fp16 (one STS.64 per column)
        {
            float sv[4], tv[4];
            #pragma unroll
            for (int q = 0; q < 4; q++) { sv[q] = sS1[rows4[q]]; tv[q] = sT1[rows4[q]]; }
            #pragma unroll
            for (int nt = 0; nt < 4; nt++)
                #pragma unroll
                for (int e = 0; e < 2; e++) {
                    int col = (h * 4 + nt) * 8 + 2 * tg + e;
                    float z0 = sv[0] * mishf(acc[0][nt][e])     + tv[0];
                    float z1 = sv[1] * mishf(acc[0][nt][2 + e]) + tv[1];
                    float z2 = sv[2] * mishf(acc[1][nt][e])     + tv[2];
                    float z3 = sv[3] * mishf(acc[1][nt][2 + e]) + tv[3];
                    if (!sMk[col]) { z0 = z1 = z2 = z3 = 0.f; }
                    int Pp = (8 * warp + g) ^ ((col >> 2) & 3);
                    uint2 pk;
                    pk.x = packh2(z0, z1);
                    pk.y = packh2(z2, z3);
                    *(uint2*)&sB[col * SBW + 2 * Pp] = pk;
                }
        }
    }
    __syncthreads();   // epi of half 1 visible to all

    // ------- depthwise conv3 + bn2 + mask, word-paired channels, in place -------
    // thread t handles logical word t (k-pos 2t, 2t+1); seg 0 -> cols 0..30, seg 1 -> 31..61.
    // cols 62,63 keep stale Y1; GEMM3 garbage there is never stored (c0 <= 60).
    {
        const int t = tid & 127, seg = tid >> 7;
        const int th = t >> 1, tl = t & 1;
        float wax = sWa[2 * t], way = sWa[2 * t + 1];
        float wbx = sWb[2 * t], wby = sWb[2 * t + 1];
        float wcx = sWc[2 * t], wcy = sWc[2 * t + 1];
        float s2x = sS2[2 * t], s2y = sS2[2 * t + 1];
        float t2x = sT2[2 * t], t2y = sT2[2 * t + 1];

        #define CADR(j) ((j) * SBW + 2 * (th ^ (((j) >> 2) & 3)) + tl)

        float2 pre31, pre32;
        if (seg == 0) {
            pre31 = __half22float2(*(__half2*)&sB[CADR(31)]);
            pre32 = __half22float2(*(__half2*)&sB[CADR(32)]);
        }
        __syncthreads();   // seg0 halo reads complete before seg1 writes cols 31,32

        int j0 = seg ? 31 : 0;
        float2 p0 = __half22float2(*(__half2*)&sB[CADR(j0)]);
        float2 p1 = __half22float2(*(__half2*)&sB[CADR(j0 + 1)]);
        #pragma unroll 2
        for (int j = j0; j < j0 + 31; j++) {
            float2 p2;
            if (seg == 0 && j == 29)      p2 = pre31;
            else if (seg == 0 && j == 30) p2 = pre32;
            else                          p2 = __half22float2(*(__half2*)&sB[CADR(j + 2)]);
            float cx = wax * p0.x + wbx * p1.x + wcx * p2.x;
            float cy = way * p0.y + wby * p1.y + wcy * p2.y;
            float vx = s2x * cx + t2x, vy = s2y * cy + t2y;
            if (!sMk[j + 1]) { vx = 0.f; vy = 0.f; }
            sB[CADR(j)] = packh2(vx, vy);
            p0 = p1; p1 = p2;
        }
        #undef CADR
    }
    __syncthreads();

    // ================ GEMM3: O = W3 @ Y2, two N-halves, direct global ================
    {
        float* ob = out + (size_t)bb * CTOT * LLEN;
        #pragma unroll
        for (int h = 0; h < 2; h++) {
            #pragma unroll
            for (int mt = 0; mt < 2; mt++)
                #pragma unroll
                for (int nt = 0; nt < 4; nt++)
                    #pragma unroll
                    for (int q = 0; q < 4; q++) acc[mt][nt][q] = 0.f;
            {
                const unsigned* wp = g_w3f + abase;
                #pragma unroll
                for (int it = 0; it < 16; it++) {
                    uint4 q1 = *(const uint4*)(wp + it * 256);
                    uint4 q2 = *(const uint4*)(wp + it * 256 + 4);
                    unsigned a0[4] = { q1.x, q1.z, q1.y, q1.w };
                    unsigned a1[4] = { q2.x, q2.z, q2.y, q2.w };
                    #pragma unroll
                    for (int nt = 0; nt < 4; nt++) {
                        const int col = (h * 4 + nt) * 8 + g;
                        const int tw = 2 * (tg ^ ((col >> 2) & 3));
                        uint2 Bv = *(const uint2*)&sB[col * SBW + it * 8 + tw];
                        mma16(acc[0][nt], a0, Bv.x, Bv.y);
                        mma16(acc[1][nt], a1, Bv.x, Bv.y);
                    }
                }
            }
            // epilogue: mish + bn3 + mask -> even output channels, STG.64 pairs
            {
                float sv[4], tv[4];
                #pragma unroll
                for (int q = 0; q < 4; q++) { sv[q] = sS3[rows4[q]]; tv[q] = sT3[rows4[q]]; }
                #pragma unroll
                for (int mt = 0; mt < 2; mt++)
                    #pragma unroll
                    for (int nt = 0; nt < 4; nt++)
                        #pragma unroll
                        for (int qp = 0; qp < 2; qp++) {
                            int ri = mt * 2 + qp;
                            int c0 = (h * 4 + nt) * 8 + 2 * tg;
                            int l = l0 + c0;
                            if (c0 < TN - 1 && l + 1 < LLEN) {
                                float y0 = mishf(acc[mt][nt][2 * qp + 0]);
                                float y1 = mishf(acc[mt][nt][2 * qp + 1]);
                                float z0 = sv[ri] * y0 + tv[ri];
                                float z1 = sv[ri] * y1 + tv[ri];
                                float2 zz;
                                zz.x = sMk[c0 + 1] ? z0 : 0.f;
                                zz.y = sMk[c0 + 2] ? z1 : 0.f;
                                *(float2*)&ob[(size_t)(2 * rows4[ri]) * LLEN + l] = zz;
                            }
                        }
            }
        }
    }
}

// ---------------- launch ----------------
extern "C" void kernel_launch(void* const* d_in, const int* in_sizes, int n_in,
                              void* d_out, int out_size) {
    (void)in_sizes; (void)n_in; (void)out_size;
    const float* x   = (const float*)d_in[0];
    const void*  mk  = d_in[1];
    const float* w1  = (const float*)d_in[2];
    const float* w2  = (const float*)d_in[3];
    const float* w3  = (const float*)d_in[4];
    const float* b1w = (const float*)d_in[5];
    const float* b1b = (const float*)d_in[6];
    const float* b1m = (const float*)d_in[7];
    const float* b1v = (const float*)d_in[8];
    const float* b2w = (const float*)d_in[9];
    const float* b2b = (const float*)d_in[10];
    const float* b2m = (const float*)d_in[11];
    const float* b2v = (const float*)d_in[12];
    const float* b3w = (const float*)d_in[13];
    const float* b3b = (const float*)d_in[14];
    const float* b3m = (const float*)d_in[15];
    const float* b3v = (const float*)d_in[16];
    float* out = (float*)d_out;

    const int smem_bytes = NCOL * SBW * (int)sizeof(unsigned);
    cudaFuncSetAttribute(fused_kernel, cudaFuncAttributeMaxDynamicSharedMemorySize, smem_bytes);

    detect_kernel<<<DET_BLOCKS, 256>>>((const unsigned char*)mk, w1, w3);

    dim3 grid(LTILES, BATCH);
    fused_kernel<<<grid, NTHREADS, smem_bytes>>>(
        x, mk,
        b1w, b1b, b1m, b1v,
        b2w, b2b, b2m, b2v,
        b3w, b3b, b3m, b3v,
        w2, out);
}